// round 1
// baseline (speedup 1.0000x reference)
#include <cuda_runtime.h>
#include <math.h>

// Problem dims (fixed per reference setup_inputs)
#define L_DIM 2048
#define S_DIM 2048
#define B_DIM 4
#define E_DIM 1024
#define N_ROWS (L_DIM * B_DIM)   // 8192 flattened (l,b) rows
#define M_MAX  2048              // max(L, S)
#define HALF_PI 1.5707963267948966f
#define EPS_F 1e-6f

// ---------------------------------------------------------------------------
// Scratch (no allocation allowed -> __device__ globals)
// ---------------------------------------------------------------------------
__device__ float g_Qp[N_ROWS * E_DIM];                 // relu(query @ Wq^T + bq), [n=(l*B+b)][f]
__device__ float g_Kp[N_ROWS * E_DIM];                 // relu(key   @ Wk^T + bk)
__device__ float g_Vp[N_ROWS * E_DIM];                 //      value @ Wv^T + bv
__device__ float g_KVs[B_DIM * E_DIM * E_DIM];         // sum_s sin(th_s) K[s,e] V[s,m]  [b][e][m]
__device__ float g_KVc[B_DIM * E_DIM * E_DIM];         // cos version
__device__ float g_Ks[B_DIM * E_DIM];                  // sum_s sin(th_s) K[s,b,e]
__device__ float g_Kc[B_DIM * E_DIM];
__device__ float g_Z[N_ROWS];                          // 1/max(denom, eps)

// ---------------------------------------------------------------------------
// Stage 1: projection GEMM.  P[n,f] = act( sum_e X[n,e]*W[f,e] + bias[f] )
// X: [N_ROWS][E] row-major (contiguous in e), W: [E][E] row-major (contig in e)
// Tile: BM=128 (n), BN=64 (f), BK=16 (e). 256 threads, 8x4 per thread.
// ---------------------------------------------------------------------------
template <bool RELU>
__global__ __launch_bounds__(256)
void proj_kernel(const float* __restrict__ X, const float* __restrict__ W,
                 const float* __restrict__ bias, float* __restrict__ P) {
    __shared__ float As[16][132];   // [k][m], transposed on load, padded
    __shared__ float Bs[16][68];    // [k][n], transposed on load, padded

    const int n0 = blockIdx.y * 128;
    const int f0 = blockIdx.x * 64;
    const int tid = threadIdx.x;
    const int ty = tid >> 4;        // 0..15 -> rows ty*8..ty*8+7
    const int tx = tid & 15;        // 0..15 -> cols tx*4..tx*4+3

    float acc[8][4];
#pragma unroll
    for (int i = 0; i < 8; i++)
#pragma unroll
        for (int j = 0; j < 4; j++) acc[i][j] = 0.f;

    for (int kt = 0; kt < E_DIM; kt += 16) {
        // A tile 128x16, transpose into As[k][m]
#pragma unroll
        for (int q = 0; q < 2; q++) {
            int lin = tid + q * 256;
            int row = lin >> 2, c4 = lin & 3;
            float4 v = *reinterpret_cast<const float4*>(&X[(n0 + row) * E_DIM + kt + c4 * 4]);
            As[c4 * 4 + 0][row] = v.x;
            As[c4 * 4 + 1][row] = v.y;
            As[c4 * 4 + 2][row] = v.z;
            As[c4 * 4 + 3][row] = v.w;
        }
        // B tile 64x16 (W rows f, contig e) -> transpose into Bs[k][f]
        {
            int row = tid >> 2, c4 = tid & 3;
            float4 v = *reinterpret_cast<const float4*>(&W[(f0 + row) * E_DIM + kt + c4 * 4]);
            Bs[c4 * 4 + 0][row] = v.x;
            Bs[c4 * 4 + 1][row] = v.y;
            Bs[c4 * 4 + 2][row] = v.z;
            Bs[c4 * 4 + 3][row] = v.w;
        }
        __syncthreads();
#pragma unroll
        for (int kk = 0; kk < 16; kk++) {
            float4 a0 = *reinterpret_cast<const float4*>(&As[kk][ty * 8]);
            float4 a1 = *reinterpret_cast<const float4*>(&As[kk][ty * 8 + 4]);
            float4 b0 = *reinterpret_cast<const float4*>(&Bs[kk][tx * 4]);
            float a[8] = {a0.x, a0.y, a0.z, a0.w, a1.x, a1.y, a1.z, a1.w};
            float bb[4] = {b0.x, b0.y, b0.z, b0.w};
#pragma unroll
            for (int i = 0; i < 8; i++)
#pragma unroll
                for (int j = 0; j < 4; j++) acc[i][j] = fmaf(a[i], bb[j], acc[i][j]);
        }
        __syncthreads();
    }

    float4 bv = *reinterpret_cast<const float4*>(&bias[f0 + tx * 4]);
    float bb[4] = {bv.x, bv.y, bv.z, bv.w};
#pragma unroll
    for (int i = 0; i < 8; i++) {
        int n = n0 + ty * 8 + i;
        float4 o;
        float r0 = acc[i][0] + bb[0];
        float r1 = acc[i][1] + bb[1];
        float r2 = acc[i][2] + bb[2];
        float r3 = acc[i][3] + bb[3];
        if (RELU) {
            r0 = fmaxf(r0, 0.f); r1 = fmaxf(r1, 0.f);
            r2 = fmaxf(r2, 0.f); r3 = fmaxf(r3, 0.f);
        }
        o.x = r0; o.y = r1; o.z = r2; o.w = r3;
        *reinterpret_cast<float4*>(&P[n * E_DIM + f0 + tx * 4]) = o;
    }
}

// ---------------------------------------------------------------------------
// Stage 2: dual KV-state GEMM (per batch).
//   KVs[b][e][m] = sum_s sin(th_s) * Kp[s,b,e] * Vp[s,b,m]   (KVc with cos)
// Reduction over s; both operands are contiguous along their tile column dim
// (e for K, m for V) -> natural smem layout, no transpose.
// Tile: BM=128 (e), BN=64 (m), BK=16 (s).
// ---------------------------------------------------------------------------
__global__ __launch_bounds__(256)
void kv_kernel() {
    __shared__ float As[16][132];   // [s][e]
    __shared__ float Bs[16][68];    // [s][m]
    __shared__ float ssin[16], scos[16];

    const int b  = blockIdx.z;
    const int e0 = blockIdx.y * 128;
    const int m0 = blockIdx.x * 64;
    const int tid = threadIdx.x;
    const int ty = tid >> 4, tx = tid & 15;

    float accS[8][4], accC[8][4];
#pragma unroll
    for (int i = 0; i < 8; i++)
#pragma unroll
        for (int j = 0; j < 4; j++) { accS[i][j] = 0.f; accC[i][j] = 0.f; }

    for (int s0 = 0; s0 < S_DIM; s0 += 16) {
        if (tid < 16) {
            float th = HALF_PI * (float)(s0 + tid + 1) / (float)M_MAX;
            ssin[tid] = sinf(th);
            scos[tid] = cosf(th);
        }
#pragma unroll
        for (int q = 0; q < 2; q++) {
            int lin = tid + q * 256;
            int ks = lin >> 5, f4 = lin & 31;
            float4 v = *reinterpret_cast<const float4*>(
                &g_Kp[((s0 + ks) * B_DIM + b) * E_DIM + e0 + f4 * 4]);
            *reinterpret_cast<float4*>(&As[ks][f4 * 4]) = v;
        }
        {
            int ks = tid >> 4, f4 = tid & 15;
            float4 v = *reinterpret_cast<const float4*>(
                &g_Vp[((s0 + ks) * B_DIM + b) * E_DIM + m0 + f4 * 4]);
            *reinterpret_cast<float4*>(&Bs[ks][f4 * 4]) = v;
        }
        __syncthreads();
#pragma unroll
        for (int kk = 0; kk < 16; kk++) {
            float4 a0 = *reinterpret_cast<const float4*>(&As[kk][ty * 8]);
            float4 a1 = *reinterpret_cast<const float4*>(&As[kk][ty * 8 + 4]);
            float4 b0 = *reinterpret_cast<const float4*>(&Bs[kk][tx * 4]);
            float a[8] = {a0.x, a0.y, a0.z, a0.w, a1.x, a1.y, a1.z, a1.w};
            float bb[4] = {b0.x, b0.y, b0.z, b0.w};
            float sa = ssin[kk], ca = scos[kk];
            float as_[8], ac_[8];
#pragma unroll
            for (int i = 0; i < 8; i++) { as_[i] = a[i] * sa; ac_[i] = a[i] * ca; }
#pragma unroll
            for (int i = 0; i < 8; i++)
#pragma unroll
                for (int j = 0; j < 4; j++) {
                    accS[i][j] = fmaf(as_[i], bb[j], accS[i][j]);
                    accC[i][j] = fmaf(ac_[i], bb[j], accC[i][j]);
                }
        }
        __syncthreads();
    }
#pragma unroll
    for (int i = 0; i < 8; i++) {
        int e = e0 + ty * 8 + i;
        float4 os = make_float4(accS[i][0], accS[i][1], accS[i][2], accS[i][3]);
        float4 oc = make_float4(accC[i][0], accC[i][1], accC[i][2], accC[i][3]);
        *reinterpret_cast<float4*>(&g_KVs[(b * E_DIM + e) * E_DIM + m0 + tx * 4]) = os;
        *reinterpret_cast<float4*>(&g_KVc[(b * E_DIM + e) * E_DIM + m0 + tx * 4]) = oc;
    }
}

// ---------------------------------------------------------------------------
// Column sums: Ks[b][e] = sum_s sin(th_s) Kp[s,b,e];  Kc with cos.
// One thread per (b,e). 4096 threads, 16 blocks; small vs GEMMs.
// ---------------------------------------------------------------------------
__global__ __launch_bounds__(256)
void colsum_kernel() {
    __shared__ float ssin[256], scos[256];
    const int idx = blockIdx.x * 256 + threadIdx.x;   // b*E + e
    const int b = idx >> 10;
    const int e = idx & 1023;
    float as0 = 0.f, ac0 = 0.f, as1 = 0.f, ac1 = 0.f;
    for (int sc = 0; sc < S_DIM; sc += 256) {
        __syncthreads();
        {
            float th = HALF_PI * (float)(sc + threadIdx.x + 1) / (float)M_MAX;
            ssin[threadIdx.x] = sinf(th);
            scos[threadIdx.x] = cosf(th);
        }
        __syncthreads();
#pragma unroll 4
        for (int j = 0; j < 256; j += 2) {
            float v0 = g_Kp[((sc + j) * B_DIM + b) * E_DIM + e];
            float v1 = g_Kp[((sc + j + 1) * B_DIM + b) * E_DIM + e];
            as0 = fmaf(ssin[j], v0, as0);
            ac0 = fmaf(scos[j], v0, ac0);
            as1 = fmaf(ssin[j + 1], v1, as1);
            ac1 = fmaf(scos[j + 1], v1, ac1);
        }
    }
    g_Ks[idx] = as0 + as1;
    g_Kc[idx] = ac0 + ac1;
}

// ---------------------------------------------------------------------------
// Normalizer: Z[n] = 1/max( sin(th_l)*dot(Qp[n],Ks[b]) + cos(th_l)*dot(Qp[n],Kc[b]), eps )
// One warp per row n = l*B+b.
// ---------------------------------------------------------------------------
__global__ __launch_bounds__(256)
void z_kernel() {
    const int warp = threadIdx.x >> 5, lane = threadIdx.x & 31;
    const int n = blockIdx.x * 8 + warp;
    const int b = n & 3, l = n >> 2;
    float ds = 0.f, dc = 0.f;
    for (int e = lane * 4; e < E_DIM; e += 128) {
        float4 q = *reinterpret_cast<const float4*>(&g_Qp[n * E_DIM + e]);
        float4 s = *reinterpret_cast<const float4*>(&g_Ks[b * E_DIM + e]);
        float4 c = *reinterpret_cast<const float4*>(&g_Kc[b * E_DIM + e]);
        ds += q.x * s.x + q.y * s.y + q.z * s.z + q.w * s.w;
        dc += q.x * c.x + q.y * c.y + q.z * c.z + q.w * c.w;
    }
#pragma unroll
    for (int o = 16; o; o >>= 1) {
        ds += __shfl_down_sync(0xFFFFFFFFu, ds, o);
        dc += __shfl_down_sync(0xFFFFFFFFu, dc, o);
    }
    if (lane == 0) {
        float th = HALF_PI * (float)(l + 1) / (float)M_MAX;
        float d = sinf(th) * ds + cosf(th) * dc;
        g_Z[n] = 1.0f / fmaxf(d, EPS_F);
    }
}

// ---------------------------------------------------------------------------
// Stage 3: output dual GEMM.
//   O[l,b,m] = Z[l,b] * ( sin(th_l)*sum_e Qp[l,b,e]*KVs[b,e,m]
//                       + cos(th_l)*sum_e Qp[l,b,e]*KVc[b,e,m] )
// Tile: BM=128 (l), BN=64 (m), BK=16 (e). A transposed on load, B natural x2.
// ---------------------------------------------------------------------------
__global__ __launch_bounds__(256)
void out_kernel(float* __restrict__ O) {
    __shared__ float As[16][132];   // [e][l], transposed
    __shared__ float Bss[16][68];   // [e][m] from KVs
    __shared__ float Bsc[16][68];   // [e][m] from KVc

    const int b  = blockIdx.z;
    const int l0 = blockIdx.y * 128;
    const int m0 = blockIdx.x * 64;
    const int tid = threadIdx.x;
    const int ty = tid >> 4, tx = tid & 15;

    float accS[8][4], accC[8][4];
#pragma unroll
    for (int i = 0; i < 8; i++)
#pragma unroll
        for (int j = 0; j < 4; j++) { accS[i][j] = 0.f; accC[i][j] = 0.f; }

    for (int kt = 0; kt < E_DIM; kt += 16) {
#pragma unroll
        for (int q = 0; q < 2; q++) {
            int lin = tid + q * 256;
            int row = lin >> 2, c4 = lin & 3;
            float4 v = *reinterpret_cast<const float4*>(
                &g_Qp[((l0 + row) * B_DIM + b) * E_DIM + kt + c4 * 4]);
            As[c4 * 4 + 0][row] = v.x;
            As[c4 * 4 + 1][row] = v.y;
            As[c4 * 4 + 2][row] = v.z;
            As[c4 * 4 + 3][row] = v.w;
        }
        {
            int ks = tid >> 4, f4 = tid & 15;
            size_t base = ((size_t)b * E_DIM + (kt + ks)) * E_DIM + m0 + f4 * 4;
            float4 vs = *reinterpret_cast<const float4*>(&g_KVs[base]);
            float4 vc = *reinterpret_cast<const float4*>(&g_KVc[base]);
            *reinterpret_cast<float4*>(&Bss[ks][f4 * 4]) = vs;
            *reinterpret_cast<float4*>(&Bsc[ks][f4 * 4]) = vc;
        }
        __syncthreads();
#pragma unroll
        for (int kk = 0; kk < 16; kk++) {
            float4 a0 = *reinterpret_cast<const float4*>(&As[kk][ty * 8]);
            float4 a1 = *reinterpret_cast<const float4*>(&As[kk][ty * 8 + 4]);
            float4 b0 = *reinterpret_cast<const float4*>(&Bss[kk][tx * 4]);
            float4 c0 = *reinterpret_cast<const float4*>(&Bsc[kk][tx * 4]);
            float a[8] = {a0.x, a0.y, a0.z, a0.w, a1.x, a1.y, a1.z, a1.w};
            float bs[4] = {b0.x, b0.y, b0.z, b0.w};
            float bc[4] = {c0.x, c0.y, c0.z, c0.w};
#pragma unroll
            for (int i = 0; i < 8; i++)
#pragma unroll
                for (int j = 0; j < 4; j++) {
                    accS[i][j] = fmaf(a[i], bs[j], accS[i][j]);
                    accC[i][j] = fmaf(a[i], bc[j], accC[i][j]);
                }
        }
        __syncthreads();
    }
#pragma unroll
    for (int i = 0; i < 8; i++) {
        int l = l0 + ty * 8 + i;
        float th = HALF_PI * (float)(l + 1) / (float)M_MAX;
        float sl = sinf(th), cl = cosf(th);
        float zz = g_Z[l * B_DIM + b];
        float4 o;
        o.x = zz * (sl * accS[i][0] + cl * accC[i][0]);
        o.y = zz * (sl * accS[i][1] + cl * accC[i][1]);
        o.z = zz * (sl * accS[i][2] + cl * accC[i][2]);
        o.w = zz * (sl * accS[i][3] + cl * accC[i][3]);
        *reinterpret_cast<float4*>(&O[((size_t)l * B_DIM + b) * E_DIM + m0 + tx * 4]) = o;
    }
}

// ---------------------------------------------------------------------------
// Launch
// ---------------------------------------------------------------------------
extern "C" void kernel_launch(void* const* d_in, const int* in_sizes, int n_in,
                              void* d_out, int out_size) {
    const float* query = (const float*)d_in[0];
    const float* key   = (const float*)d_in[1];
    const float* value = (const float*)d_in[2];
    const float* Wq    = (const float*)d_in[3];
    const float* bq    = (const float*)d_in[4];
    const float* Wk    = (const float*)d_in[5];
    const float* bk    = (const float*)d_in[6];
    const float* Wv    = (const float*)d_in[7];
    const float* bv    = (const float*)d_in[8];
    float* out = (float*)d_out;

    float *pQ, *pK, *pV;
    cudaGetSymbolAddress((void**)&pQ, g_Qp);
    cudaGetSymbolAddress((void**)&pK, g_Kp);
    cudaGetSymbolAddress((void**)&pV, g_Vp);

    dim3 projGrid(E_DIM / 64, N_ROWS / 128);   // (16, 64)
    proj_kernel<true><<<projGrid, 256>>>(query, Wq, bq, pQ);
    proj_kernel<true><<<projGrid, 256>>>(key,   Wk, bk, pK);
    proj_kernel<false><<<projGrid, 256>>>(value, Wv, bv, pV);

    colsum_kernel<<<(B_DIM * E_DIM) / 256, 256>>>();          // 16 blocks

    dim3 kvGrid(E_DIM / 64, E_DIM / 128, B_DIM);              // (16, 8, 4)
    kv_kernel<<<kvGrid, 256>>>();

    z_kernel<<<N_ROWS / 8, 256>>>();                          // 1024 blocks

    dim3 outGrid(E_DIM / 64, L_DIM / 128, B_DIM);             // (16, 16, 4)
    out_kernel<<<outGrid, 256>>>(out);
}